// round 9
// baseline (speedup 1.0000x reference)
#include <cuda_runtime.h>
#include <cstdint>

// RelationalModule via warp-level mma.sync m16n8k16 bf16 with hi/lo split.
// Inputs: 0 x_img(64*1600) 1 W0(130*32) 2 b0 3 W1 4 b1 5 W2 6 b2 7 Wp 8 bp 9 Wo 10 bo
// Output: 32 f32.

#define N_PIX 1600
#define HID   32
#define NJT   (N_PIX / 32)          // 50 j-tiles
#define NUNIT (NJT * N_PIX)         // 80,000 units (1 i x 32 j each)
#define NCTA  444                   // 3 CTAs/SM x 148 SMs, one wave
#define WPC   4                     // warps per CTA (128 threads)
#define NW    (NCTA * WPC)          // 1776 warps

__device__ __align__(16) float g_a[N_PIX * HID];   // [n][k]
__device__ __align__(16) float g_b[N_PIX * HID];   // [n][k], includes +b0
__device__ __align__(16) float g_part[NW * HID];

// ---------------------------------------------------------------------------
// helpers
// ---------------------------------------------------------------------------
__device__ __forceinline__ void splitpair(float x0, float x1,
                                          uint32_t& hi, uint32_t& lo) {
    uint32_t h;
    asm("cvt.rn.bf16x2.f32 %0, %1, %2;" : "=r"(h) : "f"(x1), "f"(x0));
    float r0 = __uint_as_float(h << 16);
    float r1 = __uint_as_float(h & 0xffff0000u);
    float d0 = x0 - r0, d1 = x1 - r1;
    uint32_t l;
    asm("cvt.rn.bf16x2.f32 %0, %1, %2;" : "=r"(l) : "f"(d1), "f"(d0));
    hi = h; lo = l;
}

__device__ __forceinline__ void mma16816(float* d, const uint32_t* a,
                                         const uint32_t* b) {
    asm("mma.sync.aligned.m16n8k16.row.col.f32.bf16.bf16.f32 "
        "{%0,%1,%2,%3}, {%4,%5,%6,%7}, {%8,%9}, {%0,%1,%2,%3};"
        : "+f"(d[0]), "+f"(d[1]), "+f"(d[2]), "+f"(d[3])
        : "r"(a[0]), "r"(a[1]), "r"(a[2]), "r"(a[3]), "r"(b[0]), "r"(b[1]));
}

// ---------------------------------------------------------------------------
// Phase 0: per-pixel embeddings, 4-way channel split for latency hiding.
// ---------------------------------------------------------------------------
__global__ void precompute_ab(const float* __restrict__ x,
                              const float* __restrict__ W0,
                              const float* __restrict__ b0) {
    int t = blockIdx.x * blockDim.x + threadIdx.x;
    if (t >= N_PIX * HID * 4) return;
    int c = t & 3;
    int k = (t >> 2) & 31;
    int n = t >> 7;
    float fa = 0.f, fb = 0.f;
    int ch0 = c * 16;
#pragma unroll
    for (int q = 0; q < 16; q++) {
        int ch = ch0 + q;
        float xv = x[ch * N_PIX + n];
        fa = fmaf(xv, W0[ch * HID + k], fa);
        fb = fmaf(xv, W0[(65 + ch) * HID + k], fb);
    }
    if (c == 0) {
        float cf = (float)n;
        fa = fmaf(cf, W0[64 * HID + k], fa);
        fb = fmaf(cf, W0[129 * HID + k], fb);
    }
    fa += __shfl_xor_sync(0xffffffffu, fa, 1);
    fa += __shfl_xor_sync(0xffffffffu, fa, 2);
    fb += __shfl_xor_sync(0xffffffffu, fb, 1);
    fb += __shfl_xor_sync(0xffffffffu, fb, 2);
    if (c == 0) {
        g_a[n * HID + k] = fa;
        g_b[n * HID + k] = fb + b0[k];
    }
}

// ---------------------------------------------------------------------------
// Phase 1: pair MLP on tensor cores (mma.sync), interleaved mt for ILP,
// 3 CTAs/SM forced via launch bounds.
// Unit = 1 i x 32 j. M=32 (2 m16 tiles), N=32 (4 n8 tiles),
// K' = 96 = [hi|lo|hi] x [Whi|Whi|Wlo].
// ---------------------------------------------------------------------------
__global__ void __launch_bounds__(128, 3)
pair_kernel(const float* __restrict__ W1, const float* __restrict__ b1,
            const float* __restrict__ W2, const float* __restrict__ b2) {
    int lane = threadIdx.x & 31;
    int warp = threadIdx.x >> 5;
    int g = lane >> 2;              // 0..7
    int t = lane & 3;               // 0..3
    int w = blockIdx.x * WPC + warp;

    // ---- B fragments (both layers, hi+lo) ----
    uint32_t B1h[2][4][2], B1l[2][4][2], B2h[2][4][2], B2l[2][4][2];
#pragma unroll
    for (int kbk = 0; kbk < 2; kbk++)
#pragma unroll
        for (int nt = 0; nt < 4; nt++)
#pragma unroll
            for (int r = 0; r < 2; r++) {
                int n = 8 * nt + g;
                int k0 = kbk * 16 + r * 8 + 2 * t;
                splitpair(W1[k0 * HID + n], W1[(k0 + 1) * HID + n],
                          B1h[kbk][nt][r], B1l[kbk][nt][r]);
                splitpair(W2[k0 * HID + n], W2[(k0 + 1) * HID + n],
                          B2h[kbk][nt][r], B2l[kbk][nt][r]);
            }
    float bias1[8], bias2[8];
#pragma unroll
    for (int nt = 0; nt < 4; nt++) {
        bias1[2 * nt + 0] = b1[8 * nt + 2 * t];
        bias1[2 * nt + 1] = b1[8 * nt + 2 * t + 1];
        bias2[2 * nt + 0] = b2[8 * nt + 2 * t];
        bias2[2 * nt + 1] = b2[8 * nt + 2 * t + 1];
    }

    float accE[4], accO[4];
#pragma unroll
    for (int nt = 0; nt < 4; nt++) { accE[nt] = 0.f; accO[nt] = 0.f; }

    const float2* ga2 = (const float2*)g_a;
    const float2* gb2 = (const float2*)g_b;

    int u0 = (int)(((long long)w * NUNIT) / NW);
    int u1 = (int)(((long long)(w + 1) * NUNIT) / NW);
    int jt = u0 / N_PIX;
    int i  = u0 - jt * N_PIX;

    for (int u = u0; u < u1; u++) {
        int j0 = jt * 32;
        float2 bv[4];
#pragma unroll
        for (int kk = 0; kk < 4; kk++)
            bv[kk] = gb2[i * 16 + kk * 4 + t];

        // ---- build h0 A-fragments (both mt tiles, interleaved) ----
        uint32_t Ah[2][2][4], Al[2][2][4];
#pragma unroll
        for (int mt = 0; mt < 2; mt++) {
            int ra = j0 + mt * 16 + g;
            int rb = ra + 8;
#pragma unroll
            for (int kbk = 0; kbk < 2; kbk++)
#pragma unroll
                for (int half = 0; half < 2; half++) {
                    int fidx = kbk * 8 + half * 4 + t;
                    float2 a0v = ga2[ra * 16 + fidx];
                    float2 a1v = ga2[rb * 16 + fidx];
                    float2 b = bv[kbk * 2 + half];
                    float h00 = fmaxf(a0v.x + b.x, 0.f);
                    float h01 = fmaxf(a0v.y + b.y, 0.f);
                    float h10 = fmaxf(a1v.x + b.x, 0.f);
                    float h11 = fmaxf(a1v.y + b.y, 0.f);
                    splitpair(h00, h01, Ah[mt][kbk][half * 2 + 0],
                                        Al[mt][kbk][half * 2 + 0]);
                    splitpair(h10, h11, Ah[mt][kbk][half * 2 + 1],
                                        Al[mt][kbk][half * 2 + 1]);
                }
        }

        // ---- layer 1 ----
        float D[2][4][4];
#pragma unroll
        for (int mt = 0; mt < 2; mt++)
#pragma unroll
            for (int nt = 0; nt < 4; nt++) {
                D[mt][nt][0] = bias1[2 * nt]; D[mt][nt][1] = bias1[2 * nt + 1];
                D[mt][nt][2] = bias1[2 * nt]; D[mt][nt][3] = bias1[2 * nt + 1];
            }
#pragma unroll
        for (int mt = 0; mt < 2; mt++)
#pragma unroll
            for (int nt = 0; nt < 4; nt++) {
                mma16816(D[mt][nt], Ah[mt][0], B1h[0][nt]);
                mma16816(D[mt][nt], Ah[mt][1], B1h[1][nt]);
                mma16816(D[mt][nt], Al[mt][0], B1h[0][nt]);
                mma16816(D[mt][nt], Al[mt][1], B1h[1][nt]);
                mma16816(D[mt][nt], Ah[mt][0], B1l[0][nt]);
                mma16816(D[mt][nt], Ah[mt][1], B1l[1][nt]);
            }

        // ---- h1 = relu(D1) -> A fragments (C->A layout identity) ----
#pragma unroll
        for (int mt = 0; mt < 2; mt++)
#pragma unroll
            for (int kbk = 0; kbk < 2; kbk++) {
                int n0 = 2 * kbk, n1 = 2 * kbk + 1;
                splitpair(fmaxf(D[mt][n0][0], 0.f), fmaxf(D[mt][n0][1], 0.f),
                          Ah[mt][kbk][0], Al[mt][kbk][0]);
                splitpair(fmaxf(D[mt][n0][2], 0.f), fmaxf(D[mt][n0][3], 0.f),
                          Ah[mt][kbk][1], Al[mt][kbk][1]);
                splitpair(fmaxf(D[mt][n1][0], 0.f), fmaxf(D[mt][n1][1], 0.f),
                          Ah[mt][kbk][2], Al[mt][kbk][2]);
                splitpair(fmaxf(D[mt][n1][2], 0.f), fmaxf(D[mt][n1][3], 0.f),
                          Ah[mt][kbk][3], Al[mt][kbk][3]);
            }

        // ---- layer 2 ----
#pragma unroll
        for (int mt = 0; mt < 2; mt++)
#pragma unroll
            for (int nt = 0; nt < 4; nt++) {
                D[mt][nt][0] = bias2[2 * nt]; D[mt][nt][1] = bias2[2 * nt + 1];
                D[mt][nt][2] = bias2[2 * nt]; D[mt][nt][3] = bias2[2 * nt + 1];
            }
#pragma unroll
        for (int mt = 0; mt < 2; mt++)
#pragma unroll
            for (int nt = 0; nt < 4; nt++) {
                mma16816(D[mt][nt], Ah[mt][0], B2h[0][nt]);
                mma16816(D[mt][nt], Ah[mt][1], B2h[1][nt]);
                mma16816(D[mt][nt], Al[mt][0], B2h[0][nt]);
                mma16816(D[mt][nt], Al[mt][1], B2h[1][nt]);
                mma16816(D[mt][nt], Ah[mt][0], B2l[0][nt]);
                mma16816(D[mt][nt], Ah[mt][1], B2l[1][nt]);
            }

        // ---- acc += relu(D2), rows folded ----
#pragma unroll
        for (int nt = 0; nt < 4; nt++) {
            accE[nt] += fmaxf(D[0][nt][0], 0.f) + fmaxf(D[0][nt][2], 0.f)
                      + fmaxf(D[1][nt][0], 0.f) + fmaxf(D[1][nt][2], 0.f);
            accO[nt] += fmaxf(D[0][nt][1], 0.f) + fmaxf(D[0][nt][3], 0.f)
                      + fmaxf(D[1][nt][1], 0.f) + fmaxf(D[1][nt][3], 0.f);
        }

        if (++i == N_PIX) { i = 0; jt++; }
    }

    // ---- reduce over the 8 g-groups (t fixed) ----
#pragma unroll
    for (int nt = 0; nt < 4; nt++) {
#pragma unroll
        for (int o = 4; o < 32; o <<= 1) {
            accE[nt] += __shfl_xor_sync(0xffffffffu, accE[nt], o);
            accO[nt] += __shfl_xor_sync(0xffffffffu, accO[nt], o);
        }
    }
    if (lane < 4) {
#pragma unroll
        for (int nt = 0; nt < 4; nt++) {
            g_part[w * HID + 8 * nt + 2 * lane + 0] = accE[nt];
            g_part[w * HID + 8 * nt + 2 * lane + 1] = accO[nt];
        }
    }
}

// ---------------------------------------------------------------------------
// Phase 2: reduce 1776 partials -> s[32]; head MLP -> out[32]
// ---------------------------------------------------------------------------
__global__ void reduce_out(const float* __restrict__ Wp, const float* __restrict__ bp,
                           const float* __restrict__ Wo, const float* __restrict__ bo,
                           float* __restrict__ out) {
    __shared__ float tmp[8][HID];
    __shared__ float s[HID], pvec[HID];
    int tid = threadIdx.x;              // 256
    int k = tid & 31, grp = tid >> 5;
    float lsum = 0.f;
    for (int b = grp; b < NW; b += 8)
        lsum += g_part[b * HID + k];
    tmp[grp][k] = lsum;
    __syncthreads();
    if (tid < HID) {
        float t = 0.f;
#pragma unroll
        for (int gg = 0; gg < 8; gg++) t += tmp[gg][tid];
        s[tid] = t;
    }
    __syncthreads();
    if (tid < HID) {
        float t = bp[tid];
#pragma unroll
        for (int kk = 0; kk < HID; kk++) t = fmaf(s[kk], Wp[kk * HID + tid], t);
        pvec[tid] = fmaxf(t, 0.f);
    }
    __syncthreads();
    if (tid < HID) {
        float t = bo[tid];
#pragma unroll
        for (int kk = 0; kk < HID; kk++) t = fmaf(pvec[kk], Wo[kk * HID + tid], t);
        out[tid] = t;
    }
}

// ---------------------------------------------------------------------------
extern "C" void kernel_launch(void* const* d_in, const int* in_sizes, int n_in,
                              void* d_out, int out_size) {
    const float* x  = (const float*)d_in[0];
    const float* W0 = (const float*)d_in[1];
    const float* b0 = (const float*)d_in[2];
    const float* W1 = (const float*)d_in[3];
    const float* b1 = (const float*)d_in[4];
    const float* W2 = (const float*)d_in[5];
    const float* b2 = (const float*)d_in[6];
    const float* Wp = (const float*)d_in[7];
    const float* bp = (const float*)d_in[8];
    const float* Wo = (const float*)d_in[9];
    const float* bo = (const float*)d_in[10];
    float* out = (float*)d_out;

    precompute_ab<<<(N_PIX * HID * 4 + 255) / 256, 256>>>(x, W0, b0);
    pair_kernel<<<NCTA, 128>>>(W1, b1, W2, b2);
    reduce_out<<<1, 256>>>(Wp, bp, Wo, bo, out);
}

// round 10
// speedup vs baseline: 1.1319x; 1.1319x over previous
#include <cuda_runtime.h>
#include <cstdint>

// RelationalModule via warp-level mma.sync m16n8k16 bf16 with hi/lo split.
// Inputs: 0 x_img(64*1600) 1 W0(130*32) 2 b0 3 W1 4 b1 5 W2 6 b2 7 Wp 8 bp 9 Wo 10 bo
// Output: 32 f32.

#define N_PIX 1600
#define HID   32
#define NJT   (N_PIX / 32)          // 50 j-tiles
#define NUNIT (NJT * N_PIX)         // 80,000 units (1 i x 32 j each)
#define NCTA  296                   // 2 CTAs/SM (R6 proven config)
#define WPC   4                     // warps per CTA (128 threads)
#define NW    (NCTA * WPC)          // 1184 warps

__device__ __align__(16) float g_a[N_PIX * HID];   // [n][k]
__device__ __align__(16) float g_b[N_PIX * HID];   // [n][k], includes +b0
__device__ __align__(16) float g_part[NW * HID];

// ---------------------------------------------------------------------------
// helpers
// ---------------------------------------------------------------------------
__device__ __forceinline__ void splitpair(float x0, float x1,
                                          uint32_t& hi, uint32_t& lo) {
    uint32_t h;
    asm("cvt.rn.bf16x2.f32 %0, %1, %2;" : "=r"(h) : "f"(x1), "f"(x0));
    float r0 = __uint_as_float(h << 16);
    float r1 = __uint_as_float(h & 0xffff0000u);
    float d0 = x0 - r0, d1 = x1 - r1;
    uint32_t l;
    asm("cvt.rn.bf16x2.f32 %0, %1, %2;" : "=r"(l) : "f"(d1), "f"(d0));
    hi = h; lo = l;
}

__device__ __forceinline__ void mma16816(float* d, const uint32_t* a,
                                         const uint32_t* b) {
    asm("mma.sync.aligned.m16n8k16.row.col.f32.bf16.bf16.f32 "
        "{%0,%1,%2,%3}, {%4,%5,%6,%7}, {%8,%9}, {%0,%1,%2,%3};"
        : "+f"(d[0]), "+f"(d[1]), "+f"(d[2]), "+f"(d[3])
        : "r"(a[0]), "r"(a[1]), "r"(a[2]), "r"(a[3]), "r"(b[0]), "r"(b[1]));
}

// ---------------------------------------------------------------------------
// Phase 0: per-pixel embeddings, 4-way channel split for latency hiding.
// ---------------------------------------------------------------------------
__global__ void precompute_ab(const float* __restrict__ x,
                              const float* __restrict__ W0,
                              const float* __restrict__ b0) {
    int t = blockIdx.x * blockDim.x + threadIdx.x;
    if (t >= N_PIX * HID * 4) return;
    int c = t & 3;
    int k = (t >> 2) & 31;
    int n = t >> 7;
    float fa = 0.f, fb = 0.f;
    int ch0 = c * 16;
#pragma unroll
    for (int q = 0; q < 16; q++) {
        int ch = ch0 + q;
        float xv = x[ch * N_PIX + n];
        fa = fmaf(xv, W0[ch * HID + k], fa);
        fb = fmaf(xv, W0[(65 + ch) * HID + k], fb);
    }
    if (c == 0) {
        float cf = (float)n;
        fa = fmaf(cf, W0[64 * HID + k], fa);
        fb = fmaf(cf, W0[129 * HID + k], fb);
    }
    fa += __shfl_xor_sync(0xffffffffu, fa, 1);
    fa += __shfl_xor_sync(0xffffffffu, fa, 2);
    fb += __shfl_xor_sync(0xffffffffu, fb, 1);
    fb += __shfl_xor_sync(0xffffffffu, fb, 2);
    if (c == 0) {
        g_a[n * HID + k] = fa;
        g_b[n * HID + k] = fb + b0[k];
    }
}

// ---------------------------------------------------------------------------
// Phase 1: pair MLP on tensor cores. Interleaved mt (ILP), a-rows hoisted
// per j-tile segment (loop-invariant), bv software-pipelined 1 iter ahead.
// Unit = 1 i x 32 j. K' = 96 = [hi|lo|hi] x [Whi|Whi|Wlo].
// ---------------------------------------------------------------------------
__global__ void __launch_bounds__(128)
pair_kernel(const float* __restrict__ W1, const float* __restrict__ b1,
            const float* __restrict__ W2, const float* __restrict__ b2) {
    int lane = threadIdx.x & 31;
    int warp = threadIdx.x >> 5;
    int g = lane >> 2;              // 0..7
    int t = lane & 3;               // 0..3
    int w = blockIdx.x * WPC + warp;

    // ---- B fragments (both layers, hi+lo) ----
    uint32_t B1h[2][4][2], B1l[2][4][2], B2h[2][4][2], B2l[2][4][2];
#pragma unroll
    for (int kbk = 0; kbk < 2; kbk++)
#pragma unroll
        for (int nt = 0; nt < 4; nt++)
#pragma unroll
            for (int r = 0; r < 2; r++) {
                int n = 8 * nt + g;
                int k0 = kbk * 16 + r * 8 + 2 * t;
                splitpair(W1[k0 * HID + n], W1[(k0 + 1) * HID + n],
                          B1h[kbk][nt][r], B1l[kbk][nt][r]);
                splitpair(W2[k0 * HID + n], W2[(k0 + 1) * HID + n],
                          B2h[kbk][nt][r], B2l[kbk][nt][r]);
            }
    float bias1[8], bias2[8];
#pragma unroll
    for (int nt = 0; nt < 4; nt++) {
        bias1[2 * nt + 0] = b1[8 * nt + 2 * t];
        bias1[2 * nt + 1] = b1[8 * nt + 2 * t + 1];
        bias2[2 * nt + 0] = b2[8 * nt + 2 * t];
        bias2[2 * nt + 1] = b2[8 * nt + 2 * t + 1];
    }

    float accE[4], accO[4];
#pragma unroll
    for (int nt = 0; nt < 4; nt++) { accE[nt] = 0.f; accO[nt] = 0.f; }

    const float2* ga2 = (const float2*)g_a;
    const float2* gb2 = (const float2*)g_b;

    int u0 = (int)(((long long)w * NUNIT) / NW);
    int u1 = (int)(((long long)(w + 1) * NUNIT) / NW);
    int u  = u0;
    int jt = u0 / N_PIX;
    int i  = u0 - jt * N_PIX;

    while (u < u1) {
        int segEnd = (jt + 1) * N_PIX;
        if (segEnd > u1) segEnd = u1;
        int j0 = jt * 32;

        // ---- hoisted a-rows for this j-tile (loop-invariant over i) ----
        float2 av[2][2][2][2];   // [mt][kbk][half][row]
#pragma unroll
        for (int mt = 0; mt < 2; mt++) {
            int ra = j0 + mt * 16 + g;
#pragma unroll
            for (int kbk = 0; kbk < 2; kbk++)
#pragma unroll
                for (int half = 0; half < 2; half++) {
                    int fidx = kbk * 8 + half * 4 + t;
                    av[mt][kbk][half][0] = ga2[ra * 16 + fidx];
                    av[mt][kbk][half][1] = ga2[(ra + 8) * 16 + fidx];
                }
        }

        // prefetch first bv of segment
        float2 bvp[4];
#pragma unroll
        for (int kk = 0; kk < 4; kk++)
            bvp[kk] = gb2[i * 16 + kk * 4 + t];

        for (; u < segEnd; ) {
            float2 bvc[4];
#pragma unroll
            for (int kk = 0; kk < 4; kk++) bvc[kk] = bvp[kk];
            u++;
            int inext = (u < segEnd) ? (i + 1) : i;   // clamped prefetch
#pragma unroll
            for (int kk = 0; kk < 4; kk++)
                bvp[kk] = gb2[inext * 16 + kk * 4 + t];

            // ---- h0 A-fragments (both mt tiles, interleaved) ----
            uint32_t Ah[2][2][4], Al[2][2][4];
#pragma unroll
            for (int mt = 0; mt < 2; mt++)
#pragma unroll
                for (int kbk = 0; kbk < 2; kbk++)
#pragma unroll
                    for (int half = 0; half < 2; half++) {
                        float2 a0v = av[mt][kbk][half][0];
                        float2 a1v = av[mt][kbk][half][1];
                        float2 b = bvc[kbk * 2 + half];
                        float h00 = fmaxf(a0v.x + b.x, 0.f);
                        float h01 = fmaxf(a0v.y + b.y, 0.f);
                        float h10 = fmaxf(a1v.x + b.x, 0.f);
                        float h11 = fmaxf(a1v.y + b.y, 0.f);
                        splitpair(h00, h01, Ah[mt][kbk][half * 2 + 0],
                                            Al[mt][kbk][half * 2 + 0]);
                        splitpair(h10, h11, Ah[mt][kbk][half * 2 + 1],
                                            Al[mt][kbk][half * 2 + 1]);
                    }

            // ---- layer 1 ----
            float D[2][4][4];
#pragma unroll
            for (int mt = 0; mt < 2; mt++)
#pragma unroll
                for (int nt = 0; nt < 4; nt++) {
                    D[mt][nt][0] = bias1[2 * nt]; D[mt][nt][1] = bias1[2 * nt + 1];
                    D[mt][nt][2] = bias1[2 * nt]; D[mt][nt][3] = bias1[2 * nt + 1];
                }
#pragma unroll
            for (int mt = 0; mt < 2; mt++)
#pragma unroll
                for (int nt = 0; nt < 4; nt++) {
                    mma16816(D[mt][nt], Ah[mt][0], B1h[0][nt]);
                    mma16816(D[mt][nt], Ah[mt][1], B1h[1][nt]);
                    mma16816(D[mt][nt], Al[mt][0], B1h[0][nt]);
                    mma16816(D[mt][nt], Al[mt][1], B1h[1][nt]);
                    mma16816(D[mt][nt], Ah[mt][0], B1l[0][nt]);
                    mma16816(D[mt][nt], Ah[mt][1], B1l[1][nt]);
                }

            // ---- h1 = relu(D1) -> A fragments (C->A layout identity) ----
#pragma unroll
            for (int mt = 0; mt < 2; mt++)
#pragma unroll
                for (int kbk = 0; kbk < 2; kbk++) {
                    int n0 = 2 * kbk, n1 = 2 * kbk + 1;
                    splitpair(fmaxf(D[mt][n0][0], 0.f), fmaxf(D[mt][n0][1], 0.f),
                              Ah[mt][kbk][0], Al[mt][kbk][0]);
                    splitpair(fmaxf(D[mt][n0][2], 0.f), fmaxf(D[mt][n0][3], 0.f),
                              Ah[mt][kbk][1], Al[mt][kbk][1]);
                    splitpair(fmaxf(D[mt][n1][0], 0.f), fmaxf(D[mt][n1][1], 0.f),
                              Ah[mt][kbk][2], Al[mt][kbk][2]);
                    splitpair(fmaxf(D[mt][n1][2], 0.f), fmaxf(D[mt][n1][3], 0.f),
                              Ah[mt][kbk][3], Al[mt][kbk][3]);
                }

            // ---- layer 2 ----
#pragma unroll
            for (int mt = 0; mt < 2; mt++)
#pragma unroll
                for (int nt = 0; nt < 4; nt++) {
                    D[mt][nt][0] = bias2[2 * nt]; D[mt][nt][1] = bias2[2 * nt + 1];
                    D[mt][nt][2] = bias2[2 * nt]; D[mt][nt][3] = bias2[2 * nt + 1];
                }
#pragma unroll
            for (int mt = 0; mt < 2; mt++)
#pragma unroll
                for (int nt = 0; nt < 4; nt++) {
                    mma16816(D[mt][nt], Ah[mt][0], B2h[0][nt]);
                    mma16816(D[mt][nt], Ah[mt][1], B2h[1][nt]);
                    mma16816(D[mt][nt], Al[mt][0], B2h[0][nt]);
                    mma16816(D[mt][nt], Al[mt][1], B2h[1][nt]);
                    mma16816(D[mt][nt], Ah[mt][0], B2l[0][nt]);
                    mma16816(D[mt][nt], Ah[mt][1], B2l[1][nt]);
                }

            // ---- acc += relu(D2), rows folded ----
#pragma unroll
            for (int nt = 0; nt < 4; nt++) {
                accE[nt] += fmaxf(D[0][nt][0], 0.f) + fmaxf(D[0][nt][2], 0.f)
                          + fmaxf(D[1][nt][0], 0.f) + fmaxf(D[1][nt][2], 0.f);
                accO[nt] += fmaxf(D[0][nt][1], 0.f) + fmaxf(D[0][nt][3], 0.f)
                          + fmaxf(D[1][nt][1], 0.f) + fmaxf(D[1][nt][3], 0.f);
            }

            i++;
        }
        if (u < u1) { jt++; i = 0; }
    }

    // ---- reduce over the 8 g-groups (t fixed) ----
#pragma unroll
    for (int nt = 0; nt < 4; nt++) {
#pragma unroll
        for (int o = 4; o < 32; o <<= 1) {
            accE[nt] += __shfl_xor_sync(0xffffffffu, accE[nt], o);
            accO[nt] += __shfl_xor_sync(0xffffffffu, accO[nt], o);
        }
    }
    if (lane < 4) {
#pragma unroll
        for (int nt = 0; nt < 4; nt++) {
            g_part[w * HID + 8 * nt + 2 * lane + 0] = accE[nt];
            g_part[w * HID + 8 * nt + 2 * lane + 1] = accO[nt];
        }
    }
}

// ---------------------------------------------------------------------------
// Phase 2: reduce 1184 partials -> s[32]; head MLP -> out[32]
// ---------------------------------------------------------------------------
__global__ void reduce_out(const float* __restrict__ Wp, const float* __restrict__ bp,
                           const float* __restrict__ Wo, const float* __restrict__ bo,
                           float* __restrict__ out) {
    __shared__ float tmp[8][HID];
    __shared__ float s[HID], pvec[HID];
    int tid = threadIdx.x;              // 256
    int k = tid & 31, grp = tid >> 5;
    float lsum = 0.f;
    for (int b = grp; b < NW; b += 8)
        lsum += g_part[b * HID + k];
    tmp[grp][k] = lsum;
    __syncthreads();
    if (tid < HID) {
        float t = 0.f;
#pragma unroll
        for (int gg = 0; gg < 8; gg++) t += tmp[gg][tid];
        s[tid] = t;
    }
    __syncthreads();
    if (tid < HID) {
        float t = bp[tid];
#pragma unroll
        for (int kk = 0; kk < HID; kk++) t = fmaf(s[kk], Wp[kk * HID + tid], t);
        pvec[tid] = fmaxf(t, 0.f);
    }
    __syncthreads();
    if (tid < HID) {
        float t = bo[tid];
#pragma unroll
        for (int kk = 0; kk < HID; kk++) t = fmaf(pvec[kk], Wo[kk * HID + tid], t);
        out[tid] = t;
    }
}

// ---------------------------------------------------------------------------
extern "C" void kernel_launch(void* const* d_in, const int* in_sizes, int n_in,
                              void* d_out, int out_size) {
    const float* x  = (const float*)d_in[0];
    const float* W0 = (const float*)d_in[1];
    const float* b0 = (const float*)d_in[2];
    const float* W1 = (const float*)d_in[3];
    const float* b1 = (const float*)d_in[4];
    const float* W2 = (const float*)d_in[5];
    const float* b2 = (const float*)d_in[6];
    const float* Wp = (const float*)d_in[7];
    const float* bp = (const float*)d_in[8];
    const float* Wo = (const float*)d_in[9];
    const float* bo = (const float*)d_in[10];
    float* out = (float*)d_out;

    precompute_ab<<<(N_PIX * HID * 4 + 255) / 256, 256>>>(x, W0, b0);
    pair_kernel<<<NCTA, 128>>>(W1, b1, W2, b2);
    reduce_out<<<1, 256>>>(Wp, bp, Wo, bo, out);
}

// round 11
// speedup vs baseline: 1.3626x; 1.2038x over previous
#include <cuda_runtime.h>
#include <cstdint>

// RelationalModule via warp-level mma.sync m16n8k16 **fp16** 2-term split.
// A (activations) split into fp16 hi+lo; W rounded to fp16 (single term).
// Inputs: 0 x_img(64*1600) 1 W0(130*32) 2 b0 3 W1 4 b1 5 W2 6 b2 7 Wp 8 bp 9 Wo 10 bo
// Output: 32 f32.

#define N_PIX 1600
#define HID   32
#define NJT   (N_PIX / 32)          // 50 j-tiles
#define NUNIT (NJT * N_PIX)         // 80,000 units (1 i x 32 j each)
#define NCTA  296                   // 2 CTAs/SM (proven config)
#define WPC   4                     // warps per CTA (128 threads)
#define NW    (NCTA * WPC)          // 1184 warps

__device__ __align__(16) float g_a[N_PIX * HID];   // [n][k]
__device__ __align__(16) float g_b[N_PIX * HID];   // [n][k], includes +b0
__device__ __align__(16) float g_part[NW * HID];

// ---------------------------------------------------------------------------
// helpers
// ---------------------------------------------------------------------------
// pack (x0 -> low f16, x1 -> high f16), plus fp16 residual pack
__device__ __forceinline__ void splitpairH(float x0, float x1,
                                           uint32_t& hi, uint32_t& lo) {
    uint32_t h;
    asm("cvt.rn.f16x2.f32 %0, %1, %2;" : "=r"(h) : "f"(x1), "f"(x0));
    float r0, r1;
    asm("{.reg .f16 lth, mth; mov.b32 {lth, mth}, %2;\n\t"
        "cvt.f32.f16 %0, lth; cvt.f32.f16 %1, mth;}"
        : "=f"(r0), "=f"(r1) : "r"(h));
    float d0 = x0 - r0, d1 = x1 - r1;
    uint32_t l;
    asm("cvt.rn.f16x2.f32 %0, %1, %2;" : "=r"(l) : "f"(d1), "f"(d0));
    hi = h; lo = l;
}
// pack two floats as fp16x2 (round only, no residual) — for weights
__device__ __forceinline__ uint32_t packH(float x0, float x1) {
    uint32_t h;
    asm("cvt.rn.f16x2.f32 %0, %1, %2;" : "=r"(h) : "f"(x1), "f"(x0));
    return h;
}

__device__ __forceinline__ void mma16816(float* d, const uint32_t* a,
                                         const uint32_t* b) {
    asm("mma.sync.aligned.m16n8k16.row.col.f32.f16.f16.f32 "
        "{%0,%1,%2,%3}, {%4,%5,%6,%7}, {%8,%9}, {%0,%1,%2,%3};"
        : "+f"(d[0]), "+f"(d[1]), "+f"(d[2]), "+f"(d[3])
        : "r"(a[0]), "r"(a[1]), "r"(a[2]), "r"(a[3]), "r"(b[0]), "r"(b[1]));
}

// ---------------------------------------------------------------------------
// Phase 0: per-pixel embeddings, 4-way channel split for latency hiding.
// ---------------------------------------------------------------------------
__global__ void precompute_ab(const float* __restrict__ x,
                              const float* __restrict__ W0,
                              const float* __restrict__ b0) {
    int t = blockIdx.x * blockDim.x + threadIdx.x;
    if (t >= N_PIX * HID * 4) return;
    int c = t & 3;
    int k = (t >> 2) & 31;
    int n = t >> 7;
    float fa = 0.f, fb = 0.f;
    int ch0 = c * 16;
#pragma unroll
    for (int q = 0; q < 16; q++) {
        int ch = ch0 + q;
        float xv = x[ch * N_PIX + n];
        fa = fmaf(xv, W0[ch * HID + k], fa);
        fb = fmaf(xv, W0[(65 + ch) * HID + k], fb);
    }
    if (c == 0) {
        float cf = (float)n;
        fa = fmaf(cf, W0[64 * HID + k], fa);
        fb = fmaf(cf, W0[129 * HID + k], fb);
    }
    fa += __shfl_xor_sync(0xffffffffu, fa, 1);
    fa += __shfl_xor_sync(0xffffffffu, fa, 2);
    fb += __shfl_xor_sync(0xffffffffu, fb, 1);
    fb += __shfl_xor_sync(0xffffffffu, fb, 2);
    if (c == 0) {
        g_a[n * HID + k] = fa;
        g_b[n * HID + k] = fb + b0[k];
    }
}

// ---------------------------------------------------------------------------
// Phase 1: pair MLP on tensor cores. fp16 2-term: D = Ah@Wh + Al@Wh.
// Interleaved mt for ILP, a-rows hoisted per j-tile, bv prefetched.
// Unit = 1 i x 32 j. 64 MMAs/unit (vs 96 for bf16 3-term).
// ---------------------------------------------------------------------------
__global__ void __launch_bounds__(128)
pair_kernel(const float* __restrict__ W1, const float* __restrict__ b1,
            const float* __restrict__ W2, const float* __restrict__ b2) {
    int lane = threadIdx.x & 31;
    int warp = threadIdx.x >> 5;
    int g = lane >> 2;              // 0..7
    int t = lane & 3;               // 0..3
    int w = blockIdx.x * WPC + warp;

    // ---- B fragments (fp16-rounded weights, both layers) ----
    uint32_t B1h[2][4][2], B2h[2][4][2];
#pragma unroll
    for (int kbk = 0; kbk < 2; kbk++)
#pragma unroll
        for (int nt = 0; nt < 4; nt++)
#pragma unroll
            for (int r = 0; r < 2; r++) {
                int n = 8 * nt + g;
                int k0 = kbk * 16 + r * 8 + 2 * t;
                B1h[kbk][nt][r] = packH(W1[k0 * HID + n], W1[(k0 + 1) * HID + n]);
                B2h[kbk][nt][r] = packH(W2[k0 * HID + n], W2[(k0 + 1) * HID + n]);
            }
    float bias1[8], bias2[8];
#pragma unroll
    for (int nt = 0; nt < 4; nt++) {
        bias1[2 * nt + 0] = b1[8 * nt + 2 * t];
        bias1[2 * nt + 1] = b1[8 * nt + 2 * t + 1];
        bias2[2 * nt + 0] = b2[8 * nt + 2 * t];
        bias2[2 * nt + 1] = b2[8 * nt + 2 * t + 1];
    }

    float accE[4], accO[4];
#pragma unroll
    for (int nt = 0; nt < 4; nt++) { accE[nt] = 0.f; accO[nt] = 0.f; }

    const float2* ga2 = (const float2*)g_a;
    const float2* gb2 = (const float2*)g_b;

    int u0 = (int)(((long long)w * NUNIT) / NW);
    int u1 = (int)(((long long)(w + 1) * NUNIT) / NW);
    int u  = u0;
    int jt = u0 / N_PIX;
    int i  = u0 - jt * N_PIX;

    while (u < u1) {
        int segEnd = (jt + 1) * N_PIX;
        if (segEnd > u1) segEnd = u1;
        int j0 = jt * 32;

        // ---- hoisted a-rows for this j-tile ----
        float2 av[2][2][2][2];   // [mt][kbk][half][row]
#pragma unroll
        for (int mt = 0; mt < 2; mt++) {
            int ra = j0 + mt * 16 + g;
#pragma unroll
            for (int kbk = 0; kbk < 2; kbk++)
#pragma unroll
                for (int half = 0; half < 2; half++) {
                    int fidx = kbk * 8 + half * 4 + t;
                    av[mt][kbk][half][0] = ga2[ra * 16 + fidx];
                    av[mt][kbk][half][1] = ga2[(ra + 8) * 16 + fidx];
                }
        }

        // prefetch first bv of segment
        float2 bvp[4];
#pragma unroll
        for (int kk = 0; kk < 4; kk++)
            bvp[kk] = gb2[i * 16 + kk * 4 + t];

        for (; u < segEnd; ) {
            float2 bvc[4];
#pragma unroll
            for (int kk = 0; kk < 4; kk++) bvc[kk] = bvp[kk];
            u++;
            int inext = (u < segEnd) ? (i + 1) : i;
#pragma unroll
            for (int kk = 0; kk < 4; kk++)
                bvp[kk] = gb2[inext * 16 + kk * 4 + t];

            // ---- h0 A-fragments (hi/lo fp16, both mt tiles) ----
            uint32_t Ah[2][2][4], Al[2][2][4];
#pragma unroll
            for (int mt = 0; mt < 2; mt++)
#pragma unroll
                for (int kbk = 0; kbk < 2; kbk++)
#pragma unroll
                    for (int half = 0; half < 2; half++) {
                        float2 a0v = av[mt][kbk][half][0];
                        float2 a1v = av[mt][kbk][half][1];
                        float2 b = bvc[kbk * 2 + half];
                        float h00 = fmaxf(a0v.x + b.x, 0.f);
                        float h01 = fmaxf(a0v.y + b.y, 0.f);
                        float h10 = fmaxf(a1v.x + b.x, 0.f);
                        float h11 = fmaxf(a1v.y + b.y, 0.f);
                        splitpairH(h00, h01, Ah[mt][kbk][half * 2 + 0],
                                             Al[mt][kbk][half * 2 + 0]);
                        splitpairH(h10, h11, Ah[mt][kbk][half * 2 + 1],
                                             Al[mt][kbk][half * 2 + 1]);
                    }

            // ---- layer 1: D = Ah@W1h + Al@W1h ----
            float D[2][4][4];
#pragma unroll
            for (int mt = 0; mt < 2; mt++)
#pragma unroll
                for (int nt = 0; nt < 4; nt++) {
                    D[mt][nt][0] = bias1[2 * nt]; D[mt][nt][1] = bias1[2 * nt + 1];
                    D[mt][nt][2] = bias1[2 * nt]; D[mt][nt][3] = bias1[2 * nt + 1];
                }
#pragma unroll
            for (int mt = 0; mt < 2; mt++)
#pragma unroll
                for (int nt = 0; nt < 4; nt++) {
                    mma16816(D[mt][nt], Ah[mt][0], B1h[0][nt]);
                    mma16816(D[mt][nt], Ah[mt][1], B1h[1][nt]);
                    mma16816(D[mt][nt], Al[mt][0], B1h[0][nt]);
                    mma16816(D[mt][nt], Al[mt][1], B1h[1][nt]);
                }

            // ---- h1 = relu(D1) -> A fragments (C->A layout identity) ----
#pragma unroll
            for (int mt = 0; mt < 2; mt++)
#pragma unroll
                for (int kbk = 0; kbk < 2; kbk++) {
                    int n0 = 2 * kbk, n1 = 2 * kbk + 1;
                    splitpairH(fmaxf(D[mt][n0][0], 0.f), fmaxf(D[mt][n0][1], 0.f),
                               Ah[mt][kbk][0], Al[mt][kbk][0]);
                    splitpairH(fmaxf(D[mt][n0][2], 0.f), fmaxf(D[mt][n0][3], 0.f),
                               Ah[mt][kbk][1], Al[mt][kbk][1]);
                    splitpairH(fmaxf(D[mt][n1][0], 0.f), fmaxf(D[mt][n1][1], 0.f),
                               Ah[mt][kbk][2], Al[mt][kbk][2]);
                    splitpairH(fmaxf(D[mt][n1][2], 0.f), fmaxf(D[mt][n1][3], 0.f),
                               Ah[mt][kbk][3], Al[mt][kbk][3]);
                }

            // ---- layer 2: D = Ah@W2h + Al@W2h ----
#pragma unroll
            for (int mt = 0; mt < 2; mt++)
#pragma unroll
                for (int nt = 0; nt < 4; nt++) {
                    D[mt][nt][0] = bias2[2 * nt]; D[mt][nt][1] = bias2[2 * nt + 1];
                    D[mt][nt][2] = bias2[2 * nt]; D[mt][nt][3] = bias2[2 * nt + 1];
                }
#pragma unroll
            for (int mt = 0; mt < 2; mt++)
#pragma unroll
                for (int nt = 0; nt < 4; nt++) {
                    mma16816(D[mt][nt], Ah[mt][0], B2h[0][nt]);
                    mma16816(D[mt][nt], Ah[mt][1], B2h[1][nt]);
                    mma16816(D[mt][nt], Al[mt][0], B2h[0][nt]);
                    mma16816(D[mt][nt], Al[mt][1], B2h[1][nt]);
                }

            // ---- acc += relu(D2), rows folded ----
#pragma unroll
            for (int nt = 0; nt < 4; nt++) {
                accE[nt] += fmaxf(D[0][nt][0], 0.f) + fmaxf(D[0][nt][2], 0.f)
                          + fmaxf(D[1][nt][0], 0.f) + fmaxf(D[1][nt][2], 0.f);
                accO[nt] += fmaxf(D[0][nt][1], 0.f) + fmaxf(D[0][nt][3], 0.f)
                          + fmaxf(D[1][nt][1], 0.f) + fmaxf(D[1][nt][3], 0.f);
            }

            i++;
        }
        if (u < u1) { jt++; i = 0; }
    }

    // ---- reduce over the 8 g-groups (t fixed) ----
#pragma unroll
    for (int nt = 0; nt < 4; nt++) {
#pragma unroll
        for (int o = 4; o < 32; o <<= 1) {
            accE[nt] += __shfl_xor_sync(0xffffffffu, accE[nt], o);
            accO[nt] += __shfl_xor_sync(0xffffffffu, accO[nt], o);
        }
    }
    if (lane < 4) {
#pragma unroll
        for (int nt = 0; nt < 4; nt++) {
            g_part[w * HID + 8 * nt + 2 * lane + 0] = accE[nt];
            g_part[w * HID + 8 * nt + 2 * lane + 1] = accO[nt];
        }
    }
}

// ---------------------------------------------------------------------------
// Phase 2: reduce 1184 partials -> s[32]; head MLP -> out[32]
// ---------------------------------------------------------------------------
__global__ void reduce_out(const float* __restrict__ Wp, const float* __restrict__ bp,
                           const float* __restrict__ Wo, const float* __restrict__ bo,
                           float* __restrict__ out) {
    __shared__ float tmp[8][HID];
    __shared__ float s[HID], pvec[HID];
    int tid = threadIdx.x;              // 256
    int k = tid & 31, grp = tid >> 5;
    float lsum = 0.f;
    for (int b = grp; b < NW; b += 8)
        lsum += g_part[b * HID + k];
    tmp[grp][k] = lsum;
    __syncthreads();
    if (tid < HID) {
        float t = 0.f;
#pragma unroll
        for (int gg = 0; gg < 8; gg++) t += tmp[gg][tid];
        s[tid] = t;
    }
    __syncthreads();
    if (tid < HID) {
        float t = bp[tid];
#pragma unroll
        for (int kk = 0; kk < HID; kk++) t = fmaf(s[kk], Wp[kk * HID + tid], t);
        pvec[tid] = fmaxf(t, 0.f);
    }
    __syncthreads();
    if (tid < HID) {
        float t = bo[tid];
#pragma unroll
        for (int kk = 0; kk < HID; kk++) t = fmaf(pvec[kk], Wo[kk * HID + tid], t);
        out[tid] = t;
    }
}

// ---------------------------------------------------------------------------
extern "C" void kernel_launch(void* const* d_in, const int* in_sizes, int n_in,
                              void* d_out, int out_size) {
    const float* x  = (const float*)d_in[0];
    const float* W0 = (const float*)d_in[1];
    const float* b0 = (const float*)d_in[2];
    const float* W1 = (const float*)d_in[3];
    const float* b1 = (const float*)d_in[4];
    const float* W2 = (const float*)d_in[5];
    const float* b2 = (const float*)d_in[6];
    const float* Wp = (const float*)d_in[7];
    const float* bp = (const float*)d_in[8];
    const float* Wo = (const float*)d_in[9];
    const float* bo = (const float*)d_in[10];
    float* out = (float*)d_out;

    precompute_ab<<<(N_PIX * HID * 4 + 255) / 256, 256>>>(x, W0, b0);
    pair_kernel<<<NCTA, 128>>>(W1, b1, W2, b2);
    reduce_out<<<1, 256>>>(Wp, bp, Wo, bo, out);
}